// round 13
// baseline (speedup 1.0000x reference)
#include <cuda_runtime.h>

// rosa_emb_layer: B=8, T=2048, V=50257, C=768
// inputs: d_in[0] = idx (B,T) int32, d_in[1] = emb (V,C) float32
// output: (B,T,C) float32
//
// R13 = R1's proven body (one row per warp, smem compare scan, rare
// backward-extend, (L<<11)|j packed max == argmax(L+j*1e-5)) with an LPT
// block schedule: occupancy is exactly 8 CTAs/SM -> 1184 slots for 2048
// CTAs (~1.73 waves), and per-CTA work ~ i_base. Ascending order put ALL
// the longest CTAs in wave 2 (anti-LPT tail). Now i_base descends with
// blockIdx (longest first, batches interleaved), so short CTAs backfill
// the stagger. Prefix-only smem fill + v8 epilogue retained.

#define TT 2048
#define BB 8
#define CC 768
#define WPB 8

__device__ __forceinline__ void stg_v8(float* p, const float* r) {
    asm volatile("st.global.v8.f32 [%0], {%1,%2,%3,%4,%5,%6,%7,%8};"
                 :: "l"(p), "f"(r[0]), "f"(r[1]), "f"(r[2]), "f"(r[3]),
                    "f"(r[4]), "f"(r[5]), "f"(r[6]), "f"(r[7]) : "memory");
}

__device__ __forceinline__ void stg_v8_zero(float* p) {
    asm volatile("st.global.v8.f32 [%0], {%1,%1,%1,%1,%1,%1,%1,%1};"
                 :: "l"(p), "f"(0.0f) : "memory");
}

__device__ __forceinline__ void ldg_v8(const float* p, float* r) {
    asm volatile("ld.global.nc.v8.f32 {%0,%1,%2,%3,%4,%5,%6,%7}, [%8];"
                 : "=f"(r[0]), "=f"(r[1]), "=f"(r[2]), "=f"(r[3]),
                   "=f"(r[4]), "=f"(r[5]), "=f"(r[6]), "=f"(r[7])
                 : "l"(p));
}

__global__ __launch_bounds__(256, 8)
void rosa_emb_kernel(const int* __restrict__ idx,
                     const float* __restrict__ emb,
                     float* __restrict__ out) {
    __shared__ int xs[TT];

    // LPT schedule: blk 0 -> heaviest rows (i_base = 2040), batches in low bits.
    const int b      = blockIdx.x & 7;
    const int blk    = blockIdx.x >> 3;             // 0..255
    const int i_base = (255 - blk) * WPB;
    const int tid  = threadIdx.x;
    const int w    = tid >> 5;
    const int lane = tid & 31;
    const int i    = i_base + w;

    // ---- Prefix-only fill: this CTA needs xs[0 .. i_base+7]. ----
    const int4* g     = (const int4*)(idx + (size_t)b * TT);
    int4*       s4    = (int4*)xs;
    const int   nfill = (i_base >> 2) + 2;
    for (int k = tid; k < nfill; k += 256) s4[k] = g[k];
    __syncthreads();

    const int xi = xs[i];
    int best = 0;                  // (L<<11)|j ; 0 == no match

    // ---- R1's proven hot loop: lanes cover j in [0,i) via int4 chunks. ----
    for (int j0 = lane * 4; j0 < i; j0 += 128) {
        const int4 v = s4[j0 >> 2];
        const bool m0 = (v.x == xi);                    // j0 < i guaranteed
        const bool m1 = (v.y == xi) & (j0 + 1 < i);
        const bool m2 = (v.z == xi) & (j0 + 2 < i);
        const bool m3 = (v.w == xi) & (j0 + 3 < i);
        if (m0 | m1 | m2 | m3) {                        // rare (~1/12500 per elt)
            #pragma unroll
            for (int c = 0; c < 4; c++) {
                const bool m = (c == 0) ? m0 : (c == 1) ? m1 : (c == 2) ? m2 : m3;
                if (m) {
                    const int j = j0 + c;
                    int L = 1, t = 1;
                    while (t <= j && xs[i - t] == xs[j - t]) { ++L; ++t; }
                    const int packed = (L << 11) | j;
                    if (packed > best) best = packed;
                }
            }
        }
    }

    // ---- Warp max-reduce the packed (L, j) score. ----
    #pragma unroll
    for (int o = 16; o; o >>= 1)
        best = max(best, __shfl_xor_sync(0xffffffffu, best, o));

    // ---- Epilogue: write this row (zeros, or emb[x[j*+1]]). ----
    float* orow = out + ((size_t)b * TT + i) * CC;
    if (best < (1 << 11)) {
        #pragma unroll
        for (int k = 0; k < 3; k++)
            stg_v8_zero(orow + (lane + 32 * k) * 8);
    } else {
        int pidx = (best & 2047) + 1;
        if (pidx > TT - 1) pidx = TT - 1;
        const int tok = xs[pidx];
        const float* erow = emb + (size_t)tok * CC;
        float rv[24];
        #pragma unroll
        for (int k = 0; k < 3; k++)
            ldg_v8(erow + (lane + 32 * k) * 8, rv + 8 * k);
        #pragma unroll
        for (int k = 0; k < 3; k++)
            stg_v8(orow + (lane + 32 * k) * 8, rv + 8 * k);
    }
}

extern "C" void kernel_launch(void* const* d_in, const int* in_sizes, int n_in,
                              void* d_out, int out_size) {
    const int*   idx = (const int*)d_in[0];
    const float* emb = (const float*)d_in[1];
    float*       out = (float*)d_out;

    rosa_emb_kernel<<<BB * (TT / WPB), 256>>>(idx, emb, out);
}

// round 14
// speedup vs baseline: 1.0151x; 1.0151x over previous
#include <cuda_runtime.h>

// rosa_emb_layer: B=8, T=2048, V=50257, C=768
// inputs: d_in[0] = idx (B,T) int32, d_in[1] = emb (V,C) float32
// output: (B,T,C) float32
//
// R14 = R1 skeleton (2048 CTAs x 8 warps, one row per warp — the only shape
// that ever hit 12.77) + per-chunk BLOOM SIGNATURES to crush the serial
// compare chain. Each 128-token chunk gets a 1024-bit smem bloom filter
// (built with atomicOr during the fill). A warp tests all full chunks in
// parallel (lane c tests chunk c: 1 LDS.32 + bit test), one ballot, and only
// hit chunks (~0.2% true + ~12% FP => ~1 avg) get the full compare scan,
// plus the masked tail chunk. Chain: 8-16 dependent trips -> ~3.
// No false negatives => correctness identical. (L<<11)|j integer max ==
// argmax(L + j*1e-5) with larger-j tie-break. v8 epilogue retained.

#define TT 2048
#define BB 8
#define CC 768
#define WPB 8
#define NCHUNK (TT / 128)          // 16
#define SIGW 32                    // 32 words = 1024 bits per chunk

__device__ __forceinline__ void stg_v8(float* p, const float* r) {
    asm volatile("st.global.v8.f32 [%0], {%1,%2,%3,%4,%5,%6,%7,%8};"
                 :: "l"(p), "f"(r[0]), "f"(r[1]), "f"(r[2]), "f"(r[3]),
                    "f"(r[4]), "f"(r[5]), "f"(r[6]), "f"(r[7]) : "memory");
}

__device__ __forceinline__ void stg_v8_zero(float* p) {
    asm volatile("st.global.v8.f32 [%0], {%1,%1,%1,%1,%1,%1,%1,%1};"
                 :: "l"(p), "f"(0.0f) : "memory");
}

__device__ __forceinline__ void ldg_v8(const float* p, float* r) {
    asm volatile("ld.global.nc.v8.f32 {%0,%1,%2,%3,%4,%5,%6,%7}, [%8];"
                 : "=f"(r[0]), "=f"(r[1]), "=f"(r[2]), "=f"(r[3]),
                   "=f"(r[4]), "=f"(r[5]), "=f"(r[6]), "=f"(r[7])
                 : "l"(p));
}

__global__ __launch_bounds__(256, 8)
void rosa_emb_kernel(const int* __restrict__ idx,
                     const float* __restrict__ emb,
                     float* __restrict__ out) {
    __shared__ int      xs[TT];
    __shared__ unsigned sig[NCHUNK * SIGW];      // 2 KB bloom signatures

    const int cta_per_b = TT / WPB;              // 256
    const int b      = blockIdx.x / cta_per_b;
    const int i_base = (blockIdx.x % cta_per_b) * WPB;
    const int tid  = threadIdx.x;
    const int w    = tid >> 5;
    const int lane = tid & 31;
    const int i    = i_base + w;

    // ---- Fill: token row (8 KB) + zero signatures. ----
    const int4* g  = (const int4*)(idx + (size_t)b * TT);
    int4*       s4 = (int4*)xs;
    s4[tid]       = g[tid];
    s4[tid + 256] = g[tid + 256];
    ((uint2*)sig)[tid] = make_uint2(0u, 0u);
    __syncthreads();

    // ---- Build bloom: each thread inserts 8 tokens (spread-addr atomics).
    #pragma unroll
    for (int k = 0; k < TT / 256; k++) {
        const int p = tid + 256 * k;
        const unsigned h = (unsigned)xs[p] & 1023u;     // 10-bit hash
        atomicOr(&sig[(p >> 7) * SIGW + (h >> 5)], 1u << (h & 31));
    }
    __syncthreads();

    const int      xi = xs[i];
    const unsigned h  = (unsigned)xi & 1023u;
    int best = 0;                   // (L<<11)|j ; 0 == no match

    // ---- Parallel signature test: lane c tests full chunk c (< i). ----
    const int nc = i >> 7;          // number of full chunks below i
    bool hit = false;
    if (lane < nc)
        hit = (sig[lane * SIGW + (h >> 5)] >> (h & 31)) & 1u;
    unsigned cmask = __ballot_sync(0xffffffffu, hit);

    // ---- Scan only hit chunks (true match + ~12% FP => ~1 avg). ----
    while (cmask) {
        const int c = __ffs(cmask) - 1;
        cmask &= cmask - 1;
        const int j0 = (c << 7) + lane * 4;              // chunk fully < i
        const int4 v = s4[j0 >> 2];
        #pragma unroll
        for (int q = 0; q < 4; q++) {
            const int e = (q == 0) ? v.x : (q == 1) ? v.y : (q == 2) ? v.z : v.w;
            if (e == xi) {
                const int j = j0 + q;
                int L = 1, t = 1;
                while (t <= j && xs[i - t] == xs[j - t]) { ++L; ++t; }
                const int p = (L << 11) | j;
                if (p > best) best = p;
            }
        }
    }

    // ---- Masked tail chunk [nc*128, i). ----
    {
        const int j0 = (nc << 7) + lane * 4;
        if (j0 < i) {
            const int4 v = s4[j0 >> 2];
            const bool m0 = (v.x == xi);
            const bool m1 = (v.y == xi) & (j0 + 1 < i);
            const bool m2 = (v.z == xi) & (j0 + 2 < i);
            const bool m3 = (v.w == xi) & (j0 + 3 < i);
            if (m0 | m1 | m2 | m3) {
                #pragma unroll
                for (int q = 0; q < 4; q++) {
                    const bool m = (q == 0) ? m0 : (q == 1) ? m1 : (q == 2) ? m2 : m3;
                    if (m) {
                        const int j = j0 + q;
                        int L = 1, t = 1;
                        while (t <= j && xs[i - t] == xs[j - t]) { ++L; ++t; }
                        const int p = (L << 11) | j;
                        if (p > best) best = p;
                    }
                }
            }
        }
    }

    // ---- Warp max-reduce the packed (L, j) score. ----
    #pragma unroll
    for (int o = 16; o; o >>= 1)
        best = max(best, __shfl_xor_sync(0xffffffffu, best, o));

    // ---- Epilogue: write this row (zeros, or emb[x[j*+1]]). ----
    float* orow = out + ((size_t)b * TT + i) * CC;
    if (best < (1 << 11)) {
        #pragma unroll
        for (int k = 0; k < 3; k++)
            stg_v8_zero(orow + (lane + 32 * k) * 8);
    } else {
        int pidx = (best & 2047) + 1;
        if (pidx > TT - 1) pidx = TT - 1;
        const int tok = xs[pidx];
        const float* erow = emb + (size_t)tok * CC;
        float rv[24];
        #pragma unroll
        for (int k = 0; k < 3; k++)
            ldg_v8(erow + (lane + 32 * k) * 8, rv + 8 * k);
        #pragma unroll
        for (int k = 0; k < 3; k++)
            stg_v8(orow + (lane + 32 * k) * 8, rv + 8 * k);
    }
}

extern "C" void kernel_launch(void* const* d_in, const int* in_sizes, int n_in,
                              void* d_out, int out_size) {
    const int*   idx = (const int*)d_in[0];
    const float* emb = (const float*)d_in[1];
    float*       out = (float*)d_out;

    rosa_emb_kernel<<<BB * (TT / WPB), 256>>>(idx, emb, out);
}